// round 17
// baseline (speedup 1.0000x reference)
#include <cuda_runtime.h>
#include <cuda_fp16.h>
#include <cstdint>
#include <math.h>

static constexpr int Bsz = 16384;
static constexpr int Hd  = 512;
static constexpr long long BH = (long long)Bsz * Hd;   // 8388608
static constexpr int WSZ = 3 * Hd * Hd;

// -------- scratch (device globals; allocation-free rule) --------
__device__ float2 g_z  [(unsigned long long)Bsz * Hd];     // gate z (fp32 complex)
__device__ __half g_rh_re[(unsigned long long)Bsz * Hd];   // r*h planes (fp16)
__device__ __half g_rh_im[(unsigned long long)Bsz * Hd];
// fp16 copies of inputs
__device__ __half g_tx_re[(unsigned long long)Bsz * Hd];
__device__ __half g_tx_im[(unsigned long long)Bsz * Hd];
__device__ __half g_th_re[(unsigned long long)Bsz * Hd];
__device__ __half g_th_im[(unsigned long long)Bsz * Hd];
__device__ __half g_tWx_re[WSZ];
__device__ __half g_tWx_im[WSZ];
__device__ __half g_tWh_re[WSZ];
__device__ __half g_tWh_im[WSZ];

// ======================= PTX helpers (base-target only) =======================
__device__ __forceinline__ uint32_t smem_u32(const void* p){
    uint32_t a;
    asm("{ .reg .u64 t; cvta.to.shared.u64 t, %1; cvt.u32.u64 %0, t; }" : "=r"(a) : "l"(p));
    return a;
}
__device__ __forceinline__ void cp16(uint32_t dst, const void* src){
    asm volatile("cp.async.cg.shared.global [%0], [%1], 16;" :: "r"(dst), "l"(src));
}
#define CP_COMMIT() asm volatile("cp.async.commit_group;" ::: "memory")
#define CP_WAIT(n)  asm volatile("cp.async.wait_group %0;" :: "n"(n) : "memory")

__device__ __forceinline__ void ldsm4(uint32_t* r, uint32_t addr){
    asm volatile("ldmatrix.sync.aligned.m8n8.x4.shared.b16 {%0,%1,%2,%3}, [%4];"
        : "=r"(r[0]), "=r"(r[1]), "=r"(r[2]), "=r"(r[3]) : "r"(addr));
}
__device__ __forceinline__ void mma16(float* c, const uint32_t* a, uint32_t b0, uint32_t b1){
    asm volatile(
        "mma.sync.aligned.m16n8k16.row.col.f32.f16.f16.f32 "
        "{%0,%1,%2,%3}, {%4,%5,%6,%7}, {%8,%9}, {%0,%1,%2,%3};"
        : "+f"(c[0]), "+f"(c[1]), "+f"(c[2]), "+f"(c[3])
        : "r"(a[0]), "r"(a[1]), "r"(a[2]), "r"(a[3]), "r"(b0), "r"(b1));
}
__device__ __forceinline__ float sigm(float x) { return 1.0f / (1.0f + expf(-x)); }

// ======================= fused K=1024 complex GEMM ===========================
// acc[m][n] = sum_k A1[m][k]*W1[g][n][k] + A2[m][k]*W2[g][n][k]   (complex fp16)
// MODE 1: g=0 -> z = sigm(acc+b); g=1 -> r = sigm(acc+b), store r*h (fp16).
// MODE 2: final: h_tilde = polar_tanh(acc+b); out = (1-z)h + z*h_tilde.
// CTA tile: TM x 128. Warps: (TM/32) x 4 of 32x32 warp tiles. Threads = TM*4.
static constexpr int NIT  = 16;                  // 1024 / 64
static constexpr int RSB  = 144;                 // row stride bytes (72 halves)

template<int MODE, int TM>
__global__ __launch_bounds__(TM * 4)
void cgemm_fused(const __half* __restrict__ A1r, const __half* __restrict__ A1i,
                 const __half* __restrict__ A2r, const __half* __restrict__ A2i,
                 const __half* __restrict__ W1r, const __half* __restrict__ W1i,
                 const __half* __restrict__ W2r, const __half* __restrict__ W2i,
                 const float* __restrict__ b1r, const float* __restrict__ b1i,
                 const float* __restrict__ b2r, const float* __restrict__ b2i,
                 const float* __restrict__ hre, const float* __restrict__ him,
                 const float2* __restrict__ zin, float2* __restrict__ zout,
                 __half* __restrict__ rhre, __half* __restrict__ rhim,
                 float2* __restrict__ outC)
{
    constexpr int NT   = TM * 4;                  // threads
    constexpr int WM   = TM / 32;                 // M warp groups
    constexpr int OArB = 0;
    constexpr int OAiB = TM * RSB;
    constexpr int OWrB = 2 * TM * RSB;
    constexpr int OWiB = (2 * TM + 128) * RSB;
    constexpr int STG_B = (2 * TM + 256) * RSB;   // stage bytes
    constexpr int NCP  = (2 * TM + 256) * 8 / NT; // cp16 per thread per stage
    constexpr int RPI  = NT / 8;                  // rows per loader step

    extern __shared__ __align__(16) char smc[];
    const int tid = threadIdx.x;
    const int w   = tid >> 5, l = tid & 31;
    const int gid = l >> 2, tig = l & 3;
    const int wm  = w % WM;                      // M group (32 rows each)
    const int wn  = w / WM;                      // 0..3 (N, 32 each)
    const int g   = blockIdx.z;
    const int mb  = blockIdx.y * TM;
    const int nb  = blockIdx.x * 128;
    const uint32_t smb = smem_u32(smc);

    const size_t gofs = (size_t)g * Hd * Hd;
    const char* pW1r = (const char*)(W1r + gofs);
    const char* pW1i = (const char*)(W1i + gofs);
    const char* pW2r = (const char*)(W2r + gofs);
    const char* pW2i = (const char*)(W2i + gofs);

    // ldmatrix per-thread byte offsets
    const int l7 = l & 7, l8 = (l >> 3) & 1, l16 = (l >> 4) & 1;
    uint32_t aoff[2], boff[2];
#pragma unroll
    for (int mi = 0; mi < 2; mi++)
        aoff[mi] = (uint32_t)((wm * 32 + mi * 16 + l8 * 8 + l7) * RSB + l16 * 16);
#pragma unroll
    for (int P = 0; P < 2; P++)
        boff[P] = (uint32_t)((wn * 32 + P * 16 + l8 * 8 + l7) * RSB + l16 * 16);

    // loader: segment 0 = (A1, W1) for kb<8, segment 1 = (A2, W2) for kb>=8
    auto load_stage = [&](int kb, int st){
        const uint32_t base = smb + st * STG_B;
        const bool s1 = (kb >= 8);
        const char* Ar = s1 ? (const char*)A2r : (const char*)A1r;
        const char* Ai = s1 ? (const char*)A2i : (const char*)A1i;
        const char* Wr = s1 ? pW2r : pW1r;
        const char* Wi = s1 ? pW2i : pW1i;
        const size_t kby = (size_t)(kb & 7) * 128;   // 64 halves
#pragma unroll
        for (int i = 0; i < NCP; i++){
            int c   = i * NT + tid;
            int row = c >> 3;
            int j   = (c & 7) * 16;
            if (row < TM){
                cp16(base + OArB + row * RSB + j, Ar + (size_t)(mb + row) * 1024 + kby + j);
            } else if (row < 2 * TM){
                int r = row - TM;
                cp16(base + OAiB + r * RSB + j,   Ai + (size_t)(mb + r) * 1024 + kby + j);
            } else if (row < 2 * TM + 128){
                int r = row - 2 * TM;
                cp16(base + OWrB + r * RSB + j,   Wr + (size_t)(nb + r) * 1024 + kby + j);
            } else {
                int r = row - (2 * TM + 128);
                cp16(base + OWiB + r * RSB + j,   Wi + (size_t)(nb + r) * 1024 + kby + j);
            }
        }
    };

    float accRe[2][4][4], accIm[2][4][4];
#pragma unroll
    for (int mi = 0; mi < 2; mi++)
#pragma unroll
        for (int nj = 0; nj < 4; nj++)
#pragma unroll
            for (int q = 0; q < 4; q++){ accRe[mi][nj][q] = 0.f; accIm[mi][nj][q] = 0.f; }

    load_stage(0, 0); CP_COMMIT();
    load_stage(1, 1); CP_COMMIT();

    for (int kb = 0; kb < NIT; kb++){
        CP_WAIT(1);
        __syncthreads();
        if (kb + 2 < NIT){
            load_stage(kb + 2, (kb + 2) % 3);
            CP_COMMIT();
        }

        const uint32_t stb = smb + (kb % 3) * STG_B;
#pragma unroll
        for (int kc = 0; kc < 4; kc++){
            const uint32_t k0b = kc * 32;        // 16 halves
            uint32_t fAr[2][4], fAi[2][4], bWr[2][4], bWi[2][4];
            ldsm4(bWr[0], stb + OWrB + boff[0] + k0b);
            ldsm4(bWr[1], stb + OWrB + boff[1] + k0b);
            ldsm4(bWi[0], stb + OWiB + boff[0] + k0b);
            ldsm4(bWi[1], stb + OWiB + boff[1] + k0b);
#pragma unroll
            for (int mi = 0; mi < 2; mi++){
                ldsm4(fAr[mi], stb + OArB + aoff[mi] + k0b);
                ldsm4(fAi[mi], stb + OAiB + aoff[mi] + k0b);
            }
#pragma unroll
            for (int nj = 0; nj < 4; nj++){
                const int P = nj >> 1, q = nj & 1;
                uint32_t br0 = bWr[P][q],     br1 = bWr[P][q + 2];
                uint32_t bi0 = bWi[P][q],     bi1 = bWi[P][q + 2];
                uint32_t bn0 = bi0 ^ 0x80008000u;   // -wi
                uint32_t bn1 = bi1 ^ 0x80008000u;
#pragma unroll
                for (int mi = 0; mi < 2; mi++){
                    mma16(accRe[mi][nj], fAr[mi], br0, br1);
                    mma16(accRe[mi][nj], fAi[mi], bn0, bn1);
                    mma16(accIm[mi][nj], fAr[mi], bi0, bi1);
                    mma16(accIm[mi][nj], fAi[mi], br0, br1);
                }
            }
        }
    }

    // ======================= fused epilogues =======================
    const float* b1rp = b1r + (size_t)g * Hd;
    const float* b1ip = b1i + (size_t)g * Hd;
    const float* b2rp = b2r + (size_t)g * Hd;
    const float* b2ip = b2i + (size_t)g * Hd;

#pragma unroll
    for (int nj = 0; nj < 4; nj++){
        const int n = nb + wn * 32 + nj * 8 + tig * 2;
        const float br0 = b1rp[n]     + b2rp[n];
        const float bi0 = b1ip[n]     + b2ip[n];
        const float br1 = b1rp[n + 1] + b2rp[n + 1];
        const float bi1 = b1ip[n + 1] + b2ip[n + 1];
#pragma unroll
        for (int mi = 0; mi < 2; mi++){
#pragma unroll
            for (int half = 0; half < 2; half++){
                const int row = mb + wm * 32 + mi * 16 + gid + half * 8;
                const size_t idx = (size_t)row * Hd + n;
                const float pr0 = accRe[mi][nj][half * 2]     + br0;
                const float pi0 = accIm[mi][nj][half * 2]     + bi0;
                const float pr1 = accRe[mi][nj][half * 2 + 1] + br1;
                const float pi1 = accIm[mi][nj][half * 2 + 1] + bi1;

                if (MODE == 1){
                    float v0r = sigm(pr0), v0i = sigm(pi0);
                    float v1r = sigm(pr1), v1i = sigm(pi1);
                    if (g == 0){
                        *(float4*)&zout[idx] = make_float4(v0r, v0i, v1r, v1i);
                    } else {
                        float2 hr = *(const float2*)&hre[idx];
                        float2 hi = *(const float2*)&him[idx];
                        __half2 rr = __floats2half2_rn(v0r * hr.x - v0i * hi.x,
                                                       v1r * hr.y - v1i * hi.y);
                        __half2 ri = __floats2half2_rn(v0r * hi.x + v0i * hr.x,
                                                       v1r * hi.y + v1i * hr.y);
                        *(__half2*)&rhre[idx] = rr;
                        *(__half2*)&rhim[idx] = ri;
                    }
                }
                else {  // MODE 2
                    float4 zv = *(const float4*)&zin[idx];
                    float2 hr = *(const float2*)&hre[idx];
                    float2 hi = *(const float2*)&him[idx];
                    float4 ov;
                    {
                        float tr = pr0, ti = pi0;
                        float mag = sqrtf(tr * tr + ti * ti);
                        float s = (mag > 0.f) ? (tanhf(mag) / mag) : 1.f;
                        float htr = s * tr, hti = s * ti;
                        float or_ = 1.f - zv.x, oi = -zv.y;
                        ov.x = or_ * hr.x - oi * hi.x + zv.x * htr - zv.y * hti;
                        ov.y = or_ * hi.x + oi * hr.x + zv.x * hti + zv.y * htr;
                    }
                    {
                        float tr = pr1, ti = pi1;
                        float mag = sqrtf(tr * tr + ti * ti);
                        float s = (mag > 0.f) ? (tanhf(mag) / mag) : 1.f;
                        float htr = s * tr, hti = s * ti;
                        float or_ = 1.f - zv.z, oi = -zv.w;
                        ov.z = or_ * hr.y - oi * hi.y + zv.z * htr - zv.w * hti;
                        ov.w = or_ * hi.y + oi * hr.y + zv.z * hti + zv.w * htr;
                    }
                    *(float4*)&outC[idx] = ov;
                }
            }
        }
    }
}

// ======================= prep: fp32 -> fp16, 8 planes, one launch =============
__global__ void to_fp16_all(const float4* __restrict__ s0, const float4* __restrict__ s1,
                            const float4* __restrict__ s2, const float4* __restrict__ s3,
                            const float4* __restrict__ s4, const float4* __restrict__ s5,
                            const float4* __restrict__ s6, const float4* __restrict__ s7,
                            __half2* __restrict__ d0, __half2* __restrict__ d1,
                            __half2* __restrict__ d2, __half2* __restrict__ d3,
                            __half2* __restrict__ d4, __half2* __restrict__ d5,
                            __half2* __restrict__ d6, __half2* __restrict__ d7,
                            int nBig, int nSmall)
{
    int i = blockIdx.x * blockDim.x + threadIdx.x;
    const float4* s; __half2* d; int n4;
    switch (blockIdx.y){
        case 0:  s = s0; d = d0; n4 = nBig;   break;
        case 1:  s = s1; d = d1; n4 = nBig;   break;
        case 2:  s = s2; d = d2; n4 = nBig;   break;
        case 3:  s = s3; d = d3; n4 = nBig;   break;
        case 4:  s = s4; d = d4; n4 = nSmall; break;
        case 5:  s = s5; d = d5; n4 = nSmall; break;
        case 6:  s = s6; d = d6; n4 = nSmall; break;
        default: s = s7; d = d7; n4 = nSmall; break;
    }
    if (i >= n4) return;
    float4 v = s[i];
    d[i * 2]     = __floats2half2_rn(v.x, v.y);
    d[i * 2 + 1] = __floats2half2_rn(v.z, v.w);
}

// ======================= launch =======================
extern "C" void kernel_launch(void* const* d_in, const int* in_sizes, int n_in,
                              void* d_out, int out_size)
{
    const float* x_re  = (const float*)d_in[0];
    const float* x_im  = (const float*)d_in[1];
    const float* h_re  = (const float*)d_in[2];
    const float* h_im  = (const float*)d_in[3];
    const float* Wx_re = (const float*)d_in[4];
    const float* Wx_im = (const float*)d_in[5];
    const float* Wh_re = (const float*)d_in[6];
    const float* Wh_im = (const float*)d_in[7];
    const float* bx_re = (const float*)d_in[8];
    const float* bx_im = (const float*)d_in[9];
    const float* bh_re = (const float*)d_in[10];
    const float* bh_im = (const float*)d_in[11];

    float2* zbuf; cudaGetSymbolAddress((void**)&zbuf, g_z);
    __half *rhre, *rhim, *txr, *txi, *thr, *thi, *wxr, *wxi, *whr, *whi;
    cudaGetSymbolAddress((void**)&rhre, g_rh_re);
    cudaGetSymbolAddress((void**)&rhim, g_rh_im);
    cudaGetSymbolAddress((void**)&txr, g_tx_re);
    cudaGetSymbolAddress((void**)&txi, g_tx_im);
    cudaGetSymbolAddress((void**)&thr, g_th_re);
    cudaGetSymbolAddress((void**)&thi, g_th_im);
    cudaGetSymbolAddress((void**)&wxr, g_tWx_re);
    cudaGetSymbolAddress((void**)&wxi, g_tWx_im);
    cudaGetSymbolAddress((void**)&whr, g_tWh_re);
    cudaGetSymbolAddress((void**)&whi, g_tWh_im);

    constexpr int SMEM_K1 = (2 * 128 + 256) * RSB * 3;   // 221184
    constexpr int SMEM_K2 = (2 * 64  + 256) * RSB * 3;   // 165888
    cudaFuncSetAttribute(cgemm_fused<1, 128>, cudaFuncAttributeMaxDynamicSharedMemorySize, SMEM_K1);
    cudaFuncSetAttribute(cgemm_fused<2, 64>,  cudaFuncAttributeMaxDynamicSharedMemorySize, SMEM_K2);

    const int nBH4 = (int)(BH / 4);
    const int nW4  = WSZ / 4;
    to_fp16_all<<<dim3((nBH4 + 255) / 256, 8), 256>>>(
        (const float4*)x_re, (const float4*)x_im, (const float4*)h_re, (const float4*)h_im,
        (const float4*)Wx_re, (const float4*)Wx_im, (const float4*)Wh_re, (const float4*)Wh_im,
        (__half2*)txr, (__half2*)txi, (__half2*)thr, (__half2*)thi,
        (__half2*)wxr, (__half2*)wxi, (__half2*)whr, (__half2*)whi, nBH4, nW4);

    // K1: z (g=0) and r -> r*h (g=1); K = [x | h] @ [Wx_g ; Wh_g].  128x128 tiles.
    dim3 grid_zr(Hd / 128, Bsz / 128, 2);
    cgemm_fused<1, 128><<<grid_zr, 512, SMEM_K1>>>(
        txr, txi, thr, thi,
        wxr, wxi, whr, whi,
        bx_re, bx_im, bh_re, bh_im,
        h_re, h_im,
        nullptr, zbuf, rhre, rhim, nullptr);

    // K2: h_tilde & final mix; K = [x | r*h] @ [Wx_2 ; Wh_2].  64x128 tiles (finer
    // granularity -> 6.9 waves instead of 3.46, killing the wave-quantization tail).
    dim3 grid_f(Hd / 128, Bsz / 64, 1);
    cgemm_fused<2, 64><<<grid_f, 256, SMEM_K2>>>(
        txr, txi, rhre, rhim,
        wxr + 2ull * Hd * Hd, wxi + 2ull * Hd * Hd,
        whr + 2ull * Hd * Hd, whi + 2ull * Hd * Hd,
        bx_re + 2 * Hd, bx_im + 2 * Hd, bh_re + 2 * Hd, bh_im + 2 * Hd,
        h_re, h_im,
        zbuf, nullptr, nullptr, nullptr, (float2*)d_out);
}